// round 7
// baseline (speedup 1.0000x reference)
#include <cuda_runtime.h>
#include <cstdint>

#define B_SZ   1024
#define HID    512
#define FEAT   32
#define CIN    4
#define KCONV  30
#define STRIDEC 6
#define LIN    924
#define TSTEPS 150
#define KDD    40
#define NSTEPS 10
#define G4     2048          // 4*HID
#define BH     (B_SZ*HID)    // 524288
#define NCTA   128
#define DYN_SMEM 73728

// ---------------- device scratch (static; no allocations) ----------------
__device__ float g_seq[TSTEPS * B_SZ * FEAT];   // conv output, [t][b][f]
__device__ float g_W0p[G4 * 544];               // packed+permuted [Wih0|Whh0], tf32-rounded
__device__ float g_W1p[G4 * 1024];              // packed+permuted [Wih1|Whh1]
__device__ float g_b0p[G4];
__device__ float g_b1p[G4];
__device__ float g_state[6 * BH];               // h0[0],h0[1],c0,h1[0],h1[1],c1
__device__ float g_y[B_SZ * FEAT];
__device__ float g_fut[NSTEPS * B_SZ * FEAT];   // [s][b][f]
__device__ float g_decwT[HID * FEAT];           // dec_w transposed [j][f]

__device__ unsigned g_count;
__device__ volatile unsigned g_gen;

// ---------------- helpers ----------------
__device__ __forceinline__ float to_tf32(float x) {
    float r;
    asm("cvt.rna.tf32.f32 %0, %1;" : "=f"(r) : "f"(x));
    return r;
}

__device__ __forceinline__ void mma_tf32(float* d, const unsigned* a, const unsigned* b) {
    asm volatile(
        "mma.sync.aligned.m16n8k8.row.col.f32.tf32.tf32.f32 "
        "{%0,%1,%2,%3}, {%4,%5,%6,%7}, {%8,%9}, {%0,%1,%2,%3};"
        : "+f"(d[0]), "+f"(d[1]), "+f"(d[2]), "+f"(d[3])
        : "r"(a[0]), "r"(a[1]), "r"(a[2]), "r"(a[3]), "r"(b[0]), "r"(b[1]));
}

// software grid barrier (sense via monotonically increasing generation)
__device__ __forceinline__ void grid_barrier(unsigned target) {
    __threadfence();
    __syncthreads();
    if (threadIdx.x == 0) {
        if (atomicAdd(&g_count, 1u) == NCTA - 1) {
            g_count = 0;
            __threadfence();
            g_gen = target;
        } else {
            while (g_gen < target) { }
            __threadfence();
        }
    }
    __syncthreads();
}

// ---------------- init ----------------
__global__ void zero_state_kernel() {
    int i = blockIdx.x * blockDim.x + threadIdx.x;
    if (i < 6 * BH) g_state[i] = 0.f;
    if (i == 0) { g_count = 0; g_gen = 0; }
}

// ---------------- encoder conv: [B,4,924] -> seq[t][b][f], relu ----------------
__global__ void conv_kernel(const float* __restrict__ x,
                            const float* __restrict__ w,
                            const float* __restrict__ bias) {
    __shared__ float xs[CIN * LIN];
    __shared__ float ws[FEAT * CIN * KCONV];
    __shared__ float bs[FEAT];
    int b = blockIdx.x;
    for (int i = threadIdx.x; i < CIN * LIN; i += blockDim.x) xs[i] = x[b * CIN * LIN + i];
    for (int i = threadIdx.x; i < FEAT * CIN * KCONV; i += blockDim.x) ws[i] = w[i];
    if (threadIdx.x < FEAT) bs[threadIdx.x] = bias[threadIdx.x];
    __syncthreads();
    for (int o = threadIdx.x; o < FEAT * TSTEPS; o += blockDim.x) {
        int f = o / TSTEPS, t = o % TSTEPS;
        float acc = bs[f];
        #pragma unroll
        for (int c = 0; c < CIN; c++) {
            const float* xr = xs + c * LIN + t * STRIDEC;
            const float* wr = ws + (f * CIN + c) * KCONV;
            #pragma unroll
            for (int k = 0; k < KCONV; k++) acc += xr[k] * wr[k];
        }
        g_seq[(t * B_SZ + b) * FEAT + f] = fmaxf(acc, 0.f);
    }
}

// ---------------- weight packing (gate-permuted, tf32-rounded) ----------------
// packed row p: blk = p>>7, gate = (p>>5)&3, u = p&31 -> original g = gate*512 + blk*32 + u
__global__ void pack_w0_kernel(const float* __restrict__ Wih, const float* __restrict__ Whh,
                               const float* __restrict__ bih, const float* __restrict__ bhh) {
    int idx = blockIdx.x * blockDim.x + threadIdx.x;
    if (idx >= G4 * 544) return;
    int p = idx / 544, k = idx - p * 544;
    int blk = p >> 7, gt = (p >> 5) & 3, u = p & 31;
    int g = gt * HID + blk * 32 + u;
    float v = (k < FEAT) ? Wih[g * FEAT + k] : Whh[g * HID + (k - FEAT)];
    g_W0p[idx] = to_tf32(v);
    if (k == 0) g_b0p[p] = bih[g] + bhh[g];
}

__global__ void pack_w1_kernel(const float* __restrict__ Wih, const float* __restrict__ Whh,
                               const float* __restrict__ bih, const float* __restrict__ bhh) {
    int idx = blockIdx.x * blockDim.x + threadIdx.x;
    if (idx >= G4 * 1024) return;
    int p = idx >> 10, k = idx & 1023;
    int blk = p >> 7, gt = (p >> 5) & 3, u = p & 31;
    int g = gt * HID + blk * 32 + u;
    float v = (k < HID) ? Wih[g * HID + k] : Whh[g * HID + (k - HID)];
    g_W1p[idx] = to_tf32(v);
    if (k == 0) g_b1p[p] = bih[g] + bhh[g];
}

__global__ void pack_dec_kernel(const float* __restrict__ dec_w) {
    int i = blockIdx.x * blockDim.x + threadIdx.x;
    if (i >= HID * FEAT) return;
    int j = i >> 5, f = i & 31;
    g_decwT[j * FEAT + f] = dec_w[f * HID + j];
}

// ---------------- LSTM step tile (per-CTA): gates 128x128 = [x|h] @ Wp^T, cell update ----
// 256 threads, 8 warps (2 warpM x 4 warpN), warp tile 64x32, tf32 m16n8k8,
// K streamed in 32-wide tiles, register+smem double buffer. (Proven in R3.)
__device__ __noinline__ void lstm_tile(const float* __restrict__ x1, int w1,
                                       const float* __restrict__ h_in, int K,
                                       const float* __restrict__ Wp,
                                       const float* __restrict__ bp,
                                       float* __restrict__ c_state,
                                       float* __restrict__ h_out,
                                       int bN, int bM, float* smem) {
    const int tid = threadIdx.x;
    const int lane = tid & 31;
    const int warp = tid >> 5;
    const int warpM = warp >> 2;   // 0..1
    const int warpN = warp & 3;    // 0..3

    const int lrow = tid >> 3;        // 0..31
    const int lc4  = (tid & 7) * 4;   // 0,4,...,28

    float acc[4][4][4];
    #pragma unroll
    for (int a = 0; a < 4; a++)
        #pragma unroll
        for (int b = 0; b < 4; b++)
            #pragma unroll
            for (int c = 0; c < 4; c++) acc[a][b][c] = 0.f;

    const int NT = K >> 5;

    auto loadA = [&](int kt, float4* ra) {
        #pragma unroll
        for (int rr = 0; rr < 4; rr++) {
            int row = lrow + rr * 32;
            int rg = bM * 128 + row;
            int k0 = kt * 32 + lc4;
            const float* src = (k0 < w1) ? (x1 + (size_t)rg * w1 + k0)
                                         : (h_in + (size_t)rg * HID + (k0 - w1));
            ra[rr] = __ldcg((const float4*)src);   // L2: h/y produced by other SMs
        }
    };
    auto loadB = [&](int kt, float4* rb) {
        #pragma unroll
        for (int rr = 0; rr < 4; rr++) {
            int row = lrow + rr * 32;
            int rg = bN * 128 + row;
            rb[rr] = *(const float4*)(Wp + (size_t)rg * K + kt * 32 + lc4);
        }
    };
    auto storeA = [&](float* As, const float4* ra) {
        #pragma unroll
        for (int rr = 0; rr < 4; rr++) {
            int row = lrow + rr * 32;
            float4 v = ra[rr];
            v.x = to_tf32(v.x); v.y = to_tf32(v.y); v.z = to_tf32(v.z); v.w = to_tf32(v.w);
            *(float4*)(As + row * 36 + lc4) = v;
        }
    };
    auto storeB = [&](float* Bs, const float4* rb) {
        #pragma unroll
        for (int rr = 0; rr < 4; rr++) {
            int row = lrow + rr * 32;
            *(float4*)(Bs + row * 36 + lc4) = rb[rr];
        }
    };
    auto compute = [&](const float* As, const float* Bs) {
        #pragma unroll
        for (int kk = 0; kk < 4; kk++) {
            unsigned af[4][4];
            #pragma unroll
            for (int mt = 0; mt < 4; mt++) {
                int r = warpM * 64 + mt * 16 + (lane >> 2);
                int c = kk * 8 + (lane & 3);
                af[mt][0] = __float_as_uint(As[r * 36 + c]);
                af[mt][1] = __float_as_uint(As[(r + 8) * 36 + c]);
                af[mt][2] = __float_as_uint(As[r * 36 + c + 4]);
                af[mt][3] = __float_as_uint(As[(r + 8) * 36 + c + 4]);
            }
            unsigned bf[4][2];
            #pragma unroll
            for (int nt = 0; nt < 4; nt++) {
                int n = warpN * 32 + nt * 8 + (lane >> 2);
                bf[nt][0] = __float_as_uint(Bs[n * 36 + kk * 8 + (lane & 3)]);
                bf[nt][1] = __float_as_uint(Bs[n * 36 + kk * 8 + (lane & 3) + 4]);
            }
            #pragma unroll
            for (int mt = 0; mt < 4; mt++)
                #pragma unroll
                for (int nt = 0; nt < 4; nt++)
                    mma_tf32(acc[mt][nt], af[mt], bf[nt]);
        }
    };

    // prologue
    {
        float4 ra[4], rb[4];
        loadA(0, ra); loadB(0, rb);
        storeA(smem, ra); storeB(smem + 4608, rb);
    }
    __syncthreads();

    int buf = 0;
    for (int kt = 0; kt < NT; kt++) {
        float4 ra[4], rb[4];
        bool more = (kt + 1 < NT);
        if (more) { loadA(kt + 1, ra); loadB(kt + 1, rb); }
        const float* As = smem + buf * 9216;
        const float* Bs = As + 4608;
        compute(As, Bs);
        if (more) {
            float* An = smem + (buf ^ 1) * 9216;
            storeA(An, ra); storeB(An + 4608, rb);
            __syncthreads();
            buf ^= 1;
        }
    }

    // epilogue: gates -> smem (stride 132), fused LSTM cell update
    __syncthreads();
    float* gs = smem;
    #pragma unroll
    for (int mt = 0; mt < 4; mt++) {
        #pragma unroll
        for (int nt = 0; nt < 4; nt++) {
            int r0 = warpM * 64 + mt * 16 + (lane >> 2);
            int c0 = warpN * 32 + nt * 8 + (lane & 3) * 2;
            gs[r0 * 132 + c0]           = acc[mt][nt][0];
            gs[r0 * 132 + c0 + 1]       = acc[mt][nt][1];
            gs[(r0 + 8) * 132 + c0]     = acc[mt][nt][2];
            gs[(r0 + 8) * 132 + c0 + 1] = acc[mt][nt][3];
        }
    }
    __syncthreads();

    int u = tid & 31;
    int brow0 = tid >> 5;
    float bi  = bp[bN * 128 + u];
    float bf_ = bp[bN * 128 + 32 + u];
    float bg  = bp[bN * 128 + 64 + u];
    float bo  = bp[bN * 128 + 96 + u];
    int j = bN * 32 + u;   // hidden unit index
    #pragma unroll
    for (int i = 0; i < 16; i++) {
        int bl = brow0 + i * 8;
        int bglob = bM * 128 + bl;
        float gi = gs[bl * 132 + u] + bi;
        float gf = gs[bl * 132 + 32 + u] + bf_;
        float gg = gs[bl * 132 + 64 + u] + bg;
        float go = gs[bl * 132 + 96 + u] + bo;
        float iv = 1.f / (1.f + __expf(-gi));
        float fv = 1.f / (1.f + __expf(-gf));
        float gv = tanhf(gg);
        float ov = 1.f / (1.f + __expf(-go));
        int idx = bglob * HID + j;
        float cn = fv * c_state[idx] + iv * gv;
        c_state[idx] = cn;
        h_out[idx] = ov * tanhf(cn);
    }
    __syncthreads();   // smem reused by caller
}

// ---------------- decoder projection tile: y = h @ dec_w^T + dec_b ----------------
// CTA handles 8 batch rows (128 CTAs x 8 = 1024); h rows staged in smem (pad 520).
__device__ __noinline__ void dec_tile(const float* __restrict__ h1,
                                      const float* __restrict__ dec_b,
                                      int slot, int cta, float* smem) {
    const int tid = threadIdx.x;
    // stage 8 rows x 512 floats
    #pragma unroll
    for (int i = 0; i < 4; i++) {
        int chunk = tid + i * 256;           // 0..1023 float4 chunks
        int row = chunk >> 7, col4 = chunk & 127;
        float4 v = __ldcg((const float4*)(h1 + (size_t)(cta * 8 + row) * HID + col4 * 4));
        *(float4*)(smem + row * 520 + col4 * 4) = v;
    }
    __syncthreads();
    const int r = tid >> 5, f = tid & 31;
    float acc = dec_b[f];
    const float* hr = smem + r * 520;
    #pragma unroll 8
    for (int jj = 0; jj < HID; jj++) acc += hr[jj] * g_decwT[jj * FEAT + f];
    int b = cta * 8 + r;
    g_y[b * FEAT + f] = acc;
    if (slot >= 0) g_fut[(slot * B_SZ + b) * FEAT + f] = acc;
    __syncthreads();
}

// ---------------- persistent kernel: full recurrence, 128 CTAs ----------------
__global__ void __launch_bounds__(256, 1) persist_kernel(const float* __restrict__ dec_b) {
    extern __shared__ float smem[];
    const int cta = blockIdx.x;
    const int bN = cta & 15, bM = cta >> 4;   // 16 gate-tiles x 8 batch-tiles

    float* h0[2] = { g_state,          g_state + BH };
    float* c0    =   g_state + 2 * BH;
    float* h1[2] = { g_state + 3 * BH, g_state + 4 * BH };
    float* c1    =   g_state + 5 * BH;

    unsigned bar = 0;
    for (int t = 0; t < TSTEPS; t++) {
        lstm_tile(g_seq + (size_t)t * B_SZ * FEAT, FEAT, h0[t & 1], 544,
                  g_W0p, g_b0p, c0, h0[(t + 1) & 1], bN, bM, smem);
        grid_barrier(++bar);
        lstm_tile(h0[(t + 1) & 1], HID, h1[t & 1], 1024,
                  g_W1p, g_b1p, c1, h1[(t + 1) & 1], bN, bM, smem);
        grid_barrier(++bar);
    }

    dec_tile(h1[0], dec_b, -1, cta, smem);   // y0 (TSTEPS even -> parity 0)
    grid_barrier(++bar);

    for (int s = 0; s < NSTEPS; s++) {
        lstm_tile(g_y, FEAT, h0[s & 1], 544,
                  g_W0p, g_b0p, c0, h0[(s + 1) & 1], bN, bM, smem);
        grid_barrier(++bar);
        lstm_tile(h0[(s + 1) & 1], HID, h1[s & 1], 1024,
                  g_W1p, g_b1p, c1, h1[(s + 1) & 1], bN, bM, smem);
        grid_barrier(++bar);
        dec_tile(h1[(s + 1) & 1], dec_b, s, cta, smem);
        grid_barrier(++bar);
    }
}

// ---------------- conv transpose: fut[b,f,10] * w[f,1,40] -> out[b,1,49] ----------------
__global__ void deconv_kernel(const float* __restrict__ dw, float* __restrict__ out) {
    __shared__ float futb[NSTEPS * FEAT];
    __shared__ float dws[FEAT * KDD];
    int b = blockIdx.x;
    for (int i = threadIdx.x; i < NSTEPS * FEAT; i += blockDim.x) {
        int t = i >> 5, f = i & 31;
        futb[i] = g_fut[(t * B_SZ + b) * FEAT + f];
    }
    for (int i = threadIdx.x; i < FEAT * KDD; i += blockDim.x) dws[i] = dw[i];
    __syncthreads();
    int jj = threadIdx.x;
    if (jj < NSTEPS + KDD - 1) {
        float acc = 0.f;
        #pragma unroll
        for (int t = 0; t < NSTEPS; t++) {
            int k = jj - t;
            if (k >= 0 && k < KDD) {
                #pragma unroll
                for (int f = 0; f < FEAT; f++) acc += futb[t * FEAT + f] * dws[f * KDD + k];
            }
        }
        out[b * (NSTEPS + KDD - 1) + jj] = acc;
    }
}

// ---------------- host ----------------
extern "C" void kernel_launch(void* const* d_in, const int* in_sizes, int n_in,
                              void* d_out, int out_size) {
    const float* x       = (const float*)d_in[0];
    const float* conv_w  = (const float*)d_in[1];
    const float* conv_b  = (const float*)d_in[2];
    const float* Wih0    = (const float*)d_in[3];
    const float* Whh0    = (const float*)d_in[4];
    const float* bih0    = (const float*)d_in[5];
    const float* bhh0    = (const float*)d_in[6];
    const float* Wih1    = (const float*)d_in[7];
    const float* Whh1    = (const float*)d_in[8];
    const float* bih1    = (const float*)d_in[9];
    const float* bhh1    = (const float*)d_in[10];
    const float* dec_w   = (const float*)d_in[11];
    const float* dec_b   = (const float*)d_in[12];
    const float* deconvw = (const float*)d_in[13];

    cudaFuncSetAttribute(persist_kernel,
                         cudaFuncAttributeMaxDynamicSharedMemorySize, DYN_SMEM);

    zero_state_kernel<<<(6 * BH + 255) / 256, 256>>>();
    conv_kernel<<<B_SZ, 256>>>(x, conv_w, conv_b);
    pack_w0_kernel<<<(G4 * 544 + 255) / 256, 256>>>(Wih0, Whh0, bih0, bhh0);
    pack_w1_kernel<<<(G4 * 1024 + 255) / 256, 256>>>(Wih1, Whh1, bih1, bhh1);
    pack_dec_kernel<<<(HID * FEAT + 255) / 256, 256>>>(dec_w);

    persist_kernel<<<NCTA, 256, DYN_SMEM>>>(dec_b);

    deconv_kernel<<<B_SZ, 64>>>(deconvw, (float*)d_out);
}

// round 8
// speedup vs baseline: 1.2834x; 1.2834x over previous
#include <cuda_runtime.h>
#include <cstdint>

#define B_SZ   1024
#define HID    512
#define FEAT   32
#define CIN    4
#define KCONV  30
#define STRIDEC 6
#define LIN    924
#define TSTEPS 150
#define KDD    40
#define NSTEPS 10
#define G4     2048          // 4*HID
#define BH     (B_SZ*HID)    // 524288
#define DYN_SMEM 147456      // 2 halves x 2 stages x (A 18KB + B 18KB)

// ---------------- device scratch (static; no allocations) ----------------
__device__ float g_seq[TSTEPS * B_SZ * FEAT];   // conv output (tf32-rounded), [t][b][f]
__device__ float g_W0p[G4 * 544];               // packed+permuted [Wih0|Whh0], tf32-rounded
__device__ float g_W1p[G4 * 1024];              // packed+permuted [Wih1|Whh1]
__device__ float g_b0p[G4];
__device__ float g_b1p[G4];
__device__ float g_state[6 * BH];               // h0[0],h0[1],c0,h1[0],h1[1],c1 (h tf32-rounded, c fp32)
__device__ float g_y[B_SZ * FEAT];              // tf32-rounded decoder output (GEMM input)
__device__ float g_fut[NSTEPS * B_SZ * FEAT];   // full-precision decoder outputs [s][b][f]
__device__ float g_decwT[HID * FEAT];           // dec_w transposed [j][f]

// ---------------- helpers ----------------
__device__ __forceinline__ float to_tf32(float x) {
    float r;
    asm("cvt.rna.tf32.f32 %0, %1;" : "=f"(r) : "f"(x));
    return r;
}
__device__ __forceinline__ uint32_t smem_u32(const void* p) {
    uint32_t a;
    asm("{ .reg .u64 t; cvta.to.shared.u64 t, %1; cvt.u32.u64 %0, t; }" : "=r"(a) : "l"(p));
    return a;
}
__device__ __forceinline__ void mma_tf32(float* d, const unsigned* a, const unsigned* b) {
    asm volatile(
        "mma.sync.aligned.m16n8k8.row.col.f32.tf32.tf32.f32 "
        "{%0,%1,%2,%3}, {%4,%5,%6,%7}, {%8,%9}, {%0,%1,%2,%3};"
        : "+f"(d[0]), "+f"(d[1]), "+f"(d[2]), "+f"(d[3])
        : "r"(a[0]), "r"(a[1]), "r"(a[2]), "r"(a[3]), "r"(b[0]), "r"(b[1]));
}
#define CP_ASYNC16(sa, gp) \
    asm volatile("cp.async.cg.shared.global [%0], [%1], 16;" :: "r"(sa), "l"(gp))
#define CP_COMMIT() asm volatile("cp.async.commit_group;" ::: "memory")
#define CP_WAIT1()  asm volatile("cp.async.wait_group 1;" ::: "memory")
#define CP_WAIT0()  asm volatile("cp.async.wait_group 0;" ::: "memory")
#define BARH(h) asm volatile("bar.sync %0, 128;" :: "r"(1 + (h)) : "memory")

// ---------------- fused setup: zero state + pack weights (one launch) ----------------
__global__ void setup_kernel(const float* __restrict__ Wih0, const float* __restrict__ Whh0,
                             const float* __restrict__ bih0, const float* __restrict__ bhh0,
                             const float* __restrict__ Wih1, const float* __restrict__ Whh1,
                             const float* __restrict__ bih1, const float* __restrict__ bhh1,
                             const float* __restrict__ dec_w) {
    long i = (long)blockIdx.x * blockDim.x + threadIdx.x;
    if (i < 6L * BH) { g_state[i] = 0.f; return; }
    long j = i - 6L * BH;
    if (j < (long)G4 * 544) {
        int p = (int)(j / 544), k = (int)(j - (long)p * 544);
        int blk = p >> 7, gt = (p >> 5) & 3, u = p & 31;
        int g = gt * HID + blk * 32 + u;
        float v = (k < FEAT) ? Wih0[g * FEAT + k] : Whh0[g * HID + (k - FEAT)];
        g_W0p[j] = to_tf32(v);
        if (k == 0) g_b0p[p] = bih0[g] + bhh0[g];
        return;
    }
    long k2 = j - (long)G4 * 544;
    if (k2 < (long)G4 * 1024) {
        int p = (int)(k2 >> 10), k = (int)(k2 & 1023);
        int blk = p >> 7, gt = (p >> 5) & 3, u = p & 31;
        int g = gt * HID + blk * 32 + u;
        float v = (k < HID) ? Wih1[g * HID + k] : Whh1[g * HID + (k - HID)];
        g_W1p[k2] = to_tf32(v);
        if (k == 0) g_b1p[p] = bih1[g] + bhh1[g];
        return;
    }
    long k3 = k2 - (long)G4 * 1024;
    if (k3 < (long)HID * FEAT) {
        int jj = (int)(k3 >> 5), f = (int)(k3 & 31);
        g_decwT[jj * FEAT + f] = dec_w[f * HID + jj];
    }
}
#define SETUP_ITEMS (6L * BH + (long)G4 * 544 + (long)G4 * 1024 + (long)HID * FEAT)

// ---------------- encoder conv: [B,4,924] -> seq[t][b][f], relu, tf32-rounded ------
__global__ void conv_kernel(const float* __restrict__ x,
                            const float* __restrict__ w,
                            const float* __restrict__ bias) {
    __shared__ float xs[CIN * LIN];
    __shared__ float ws[FEAT * CIN * KCONV];
    __shared__ float bs[FEAT];
    int b = blockIdx.x;
    for (int i = threadIdx.x; i < CIN * LIN; i += blockDim.x) xs[i] = x[b * CIN * LIN + i];
    for (int i = threadIdx.x; i < FEAT * CIN * KCONV; i += blockDim.x) ws[i] = w[i];
    if (threadIdx.x < FEAT) bs[threadIdx.x] = bias[threadIdx.x];
    __syncthreads();
    for (int o = threadIdx.x; o < FEAT * TSTEPS; o += blockDim.x) {
        int f = o / TSTEPS, t = o % TSTEPS;
        float acc = bs[f];
        #pragma unroll
        for (int c = 0; c < CIN; c++) {
            const float* xr = xs + c * LIN + t * STRIDEC;
            const float* wr = ws + (f * CIN + c) * KCONV;
            #pragma unroll
            for (int k = 0; k < KCONV; k++) acc += xr[k] * wr[k];
        }
        g_seq[(t * B_SZ + b) * FEAT + f] = to_tf32(fmaxf(acc, 0.f));
    }
}

// ---------------- split-K fused LSTM step ----------------
// CTA tile 128x128 (bM batch, bN packed-gates). 8 warps: half = warp>>2 owns a
// disjoint k-tile subset (kt ≡ half mod 2); per half a 2x2 grid of 64x64 warp
// tiles. cp.async double buffer per half with named barriers. Halves reduce
// partials in smem, then fused LSTM cell update.
__global__ void __launch_bounds__(256, 1)
lstm_step_kernel(const float* __restrict__ x1, int w1,
                 const float* __restrict__ h_in, int K,
                 const float* __restrict__ Wp, const float* __restrict__ bp,
                 float* __restrict__ c_state, float* __restrict__ h_out) {
    extern __shared__ float smem[];
    const int tid  = threadIdx.x;
    const int lane = tid & 31;
    const int warp = tid >> 5;
    const int half = warp >> 2;
    const int wl   = warp & 3;
    const int wm   = wl >> 1;      // 0..1 : 64-row band
    const int wn   = wl & 1;       // 0..1 : 64-col band
    const int t128 = tid & 127;
    const int bN = blockIdx.x, bM = blockIdx.y;
    const int NT = K >> 5;

    float* hbase = smem + half * 18432;    // per-half area: 2 stages x 9216 floats

    float acc[4][8][4];
    #pragma unroll
    for (int a = 0; a < 4; a++)
        #pragma unroll
        for (int b = 0; b < 8; b++)
            #pragma unroll
            for (int c = 0; c < 4; c++) acc[a][b][c] = 0.f;

    auto prefetch = [&](int kt, int s) {
        float* As = hbase + s * 9216;
        float* Bs = As + 4608;
        uint32_t a_s = smem_u32(As), b_s = smem_u32(Bs);
        const int k0 = kt * 32;
        #pragma unroll
        for (int i = 0; i < 8; i++) {
            int chunk = t128 + i * 128;
            int row = chunk >> 3, c4 = (chunk & 7) * 4;
            const float* src = (k0 < w1)
                ? x1 + (size_t)(bM * 128 + row) * w1 + k0 + c4
                : h_in + (size_t)(bM * 128 + row) * HID + (k0 - w1) + c4;
            CP_ASYNC16(a_s + (uint32_t)(row * 36 + c4) * 4u, src);
        }
        #pragma unroll
        for (int i = 0; i < 8; i++) {
            int chunk = t128 + i * 128;
            int row = chunk >> 3, c4 = (chunk & 7) * 4;
            CP_ASYNC16(b_s + (uint32_t)(row * 36 + c4) * 4u,
                       Wp + (size_t)(bN * 128 + row) * K + k0 + c4);
        }
    };

    auto compute = [&](int s) {
        const float* As = hbase + s * 9216;
        const float* Bs = As + 4608;
        #pragma unroll
        for (int kk = 0; kk < 4; kk++) {
            unsigned af[4][4];
            #pragma unroll
            for (int mt = 0; mt < 4; mt++) {
                int r = wm * 64 + mt * 16 + (lane >> 2);
                int c = kk * 8 + (lane & 3);
                af[mt][0] = __float_as_uint(As[r * 36 + c]);
                af[mt][1] = __float_as_uint(As[(r + 8) * 36 + c]);
                af[mt][2] = __float_as_uint(As[r * 36 + c + 4]);
                af[mt][3] = __float_as_uint(As[(r + 8) * 36 + c + 4]);
            }
            unsigned bf[8][2];
            #pragma unroll
            for (int nt = 0; nt < 8; nt++) {
                int n = wn * 64 + nt * 8 + (lane >> 2);
                bf[nt][0] = __float_as_uint(Bs[n * 36 + kk * 8 + (lane & 3)]);
                bf[nt][1] = __float_as_uint(Bs[n * 36 + kk * 8 + (lane & 3) + 4]);
            }
            #pragma unroll
            for (int mt = 0; mt < 4; mt++)
                #pragma unroll
                for (int nt = 0; nt < 8; nt++)
                    mma_tf32(acc[mt][nt], af[mt], bf[nt]);
        }
    };

    // per-half pipelined mainloop over k-tiles kt = half, half+2, ...
    prefetch(half, 0);
    CP_COMMIT();
    if (half + 2 < NT) prefetch(half + 2, 1);
    CP_COMMIT();
    int buf = 0;
    for (int kt = half; kt < NT; kt += 2) {
        if (kt + 2 < NT) { CP_WAIT1(); } else { CP_WAIT0(); }
        BARH(half);
        compute(buf);
        BARH(half);
        if (kt + 4 < NT) prefetch(kt + 4, buf);
        CP_COMMIT();
        buf ^= 1;
    }

    // ---- cross-half reduction into gs (stride 132), then cell update ----
    __syncthreads();
    float* gs = smem;
    if (half == 1) {
        #pragma unroll
        for (int mt = 0; mt < 4; mt++)
            #pragma unroll
            for (int nt = 0; nt < 8; nt++) {
                int r0 = wm * 64 + mt * 16 + (lane >> 2);
                int c0 = wn * 64 + nt * 8 + (lane & 3) * 2;
                gs[r0 * 132 + c0]           = acc[mt][nt][0];
                gs[r0 * 132 + c0 + 1]       = acc[mt][nt][1];
                gs[(r0 + 8) * 132 + c0]     = acc[mt][nt][2];
                gs[(r0 + 8) * 132 + c0 + 1] = acc[mt][nt][3];
            }
    }
    __syncthreads();
    if (half == 0) {
        #pragma unroll
        for (int mt = 0; mt < 4; mt++)
            #pragma unroll
            for (int nt = 0; nt < 8; nt++) {
                int r0 = wm * 64 + mt * 16 + (lane >> 2);
                int c0 = wn * 64 + nt * 8 + (lane & 3) * 2;
                gs[r0 * 132 + c0]           += acc[mt][nt][0];
                gs[r0 * 132 + c0 + 1]       += acc[mt][nt][1];
                gs[(r0 + 8) * 132 + c0]     += acc[mt][nt][2];
                gs[(r0 + 8) * 132 + c0 + 1] += acc[mt][nt][3];
            }
    }
    __syncthreads();

    {
        int u = tid & 31;
        int brow0 = tid >> 5;
        float bi  = bp[bN * 128 + u];
        float bf_ = bp[bN * 128 + 32 + u];
        float bg  = bp[bN * 128 + 64 + u];
        float bo  = bp[bN * 128 + 96 + u];
        int j = bN * 32 + u;   // hidden unit index
        #pragma unroll
        for (int i = 0; i < 16; i++) {
            int bl = brow0 + i * 8;
            int bglob = bM * 128 + bl;
            float gi = gs[bl * 132 + u] + bi;
            float gf = gs[bl * 132 + 32 + u] + bf_;
            float gg = gs[bl * 132 + 64 + u] + bg;
            float go = gs[bl * 132 + 96 + u] + bo;
            float iv = 1.f / (1.f + __expf(-gi));
            float fv = 1.f / (1.f + __expf(-gf));
            float gv = tanhf(gg);
            float ov = 1.f / (1.f + __expf(-go));
            int idx = bglob * HID + j;
            float cn = fv * c_state[idx] + iv * gv;
            c_state[idx] = cn;
            h_out[idx] = to_tf32(ov * tanhf(cn));   // GEMM operand: pre-rounded
        }
    }
}

// ---------------- decoder projection: y = h @ dec_w^T + dec_b ----------------
__global__ void dec_out_kernel(const float* __restrict__ h, float* __restrict__ y,
                               const float* __restrict__ dec_b, int slot) {
    int g = blockIdx.x * blockDim.x + threadIdx.x;  // 32768
    int b = g >> 5, f = g & 31;
    float acc = dec_b[f];
    const float* hr = h + b * HID;
    #pragma unroll 8
    for (int j = 0; j < HID; j++) acc += hr[j] * g_decwT[j * FEAT + f];
    y[b * FEAT + f] = to_tf32(acc);                 // GEMM operand: pre-rounded
    if (slot >= 0) g_fut[(slot * B_SZ + b) * FEAT + f] = acc;  // full precision for output
}

// ---------------- conv transpose: fut[b,f,10] * w[f,1,40] -> out[b,1,49] ----------------
__global__ void deconv_kernel(const float* __restrict__ dw, float* __restrict__ out) {
    __shared__ float futb[NSTEPS * FEAT];
    __shared__ float dws[FEAT * KDD];
    int b = blockIdx.x;
    for (int i = threadIdx.x; i < NSTEPS * FEAT; i += blockDim.x) {
        int t = i >> 5, f = i & 31;
        futb[i] = g_fut[(t * B_SZ + b) * FEAT + f];
    }
    for (int i = threadIdx.x; i < FEAT * KDD; i += blockDim.x) dws[i] = dw[i];
    __syncthreads();
    int jj = threadIdx.x;
    if (jj < NSTEPS + KDD - 1) {
        float acc = 0.f;
        #pragma unroll
        for (int t = 0; t < NSTEPS; t++) {
            int k = jj - t;
            if (k >= 0 && k < KDD) {
                #pragma unroll
                for (int f = 0; f < FEAT; f++) acc += futb[t * FEAT + f] * dws[f * KDD + k];
            }
        }
        out[b * (NSTEPS + KDD - 1) + jj] = acc;
    }
}

// ---------------- host ----------------
extern "C" void kernel_launch(void* const* d_in, const int* in_sizes, int n_in,
                              void* d_out, int out_size) {
    const float* x       = (const float*)d_in[0];
    const float* conv_w  = (const float*)d_in[1];
    const float* conv_b  = (const float*)d_in[2];
    const float* Wih0    = (const float*)d_in[3];
    const float* Whh0    = (const float*)d_in[4];
    const float* bih0    = (const float*)d_in[5];
    const float* bhh0    = (const float*)d_in[6];
    const float* Wih1    = (const float*)d_in[7];
    const float* Whh1    = (const float*)d_in[8];
    const float* bih1    = (const float*)d_in[9];
    const float* bhh1    = (const float*)d_in[10];
    const float* dec_w   = (const float*)d_in[11];
    const float* dec_b   = (const float*)d_in[12];
    const float* deconvw = (const float*)d_in[13];

    cudaFuncSetAttribute(lstm_step_kernel,
                         cudaFuncAttributeMaxDynamicSharedMemorySize, DYN_SMEM);

    float *seq, *state, *yb, *W0p, *W1p, *b0p, *b1p;
    cudaGetSymbolAddress((void**)&seq,   g_seq);
    cudaGetSymbolAddress((void**)&state, g_state);
    cudaGetSymbolAddress((void**)&yb,    g_y);
    cudaGetSymbolAddress((void**)&W0p,   g_W0p);
    cudaGetSymbolAddress((void**)&W1p,   g_W1p);
    cudaGetSymbolAddress((void**)&b0p,   g_b0p);
    cudaGetSymbolAddress((void**)&b1p,   g_b1p);

    float* h0[2] = { state,          state + BH };
    float* c0    =   state + 2 * BH;
    float* h1[2] = { state + 3 * BH, state + 4 * BH };
    float* c1    =   state + 5 * BH;

    // launch order puts the K=1024 step at harness index 3 (= ncu -s 5 window)
    setup_kernel<<<(int)((SETUP_ITEMS + 255) / 256), 256>>>(Wih0, Whh0, bih0, bhh0,
                                                            Wih1, Whh1, bih1, bhh1, dec_w);
    conv_kernel<<<B_SZ, 256>>>(x, conv_w, conv_b);

    dim3 sgrid(16, 8), sblk(256);
    for (int t = 0; t < TSTEPS; t++) {
        lstm_step_kernel<<<sgrid, sblk, DYN_SMEM>>>(seq + (size_t)t * B_SZ * FEAT, FEAT,
                                                    h0[t & 1], 544, W0p, b0p, c0, h0[(t + 1) & 1]);
        lstm_step_kernel<<<sgrid, sblk, DYN_SMEM>>>(h0[(t + 1) & 1], HID,
                                                    h1[t & 1], 1024, W1p, b1p, c1, h1[(t + 1) & 1]);
    }

    // y0 = h1_final @ dec_w^T + dec_b   (TSTEPS even -> final parity 0)
    dec_out_kernel<<<128, 256>>>(h1[0], yb, dec_b, -1);

    for (int s = 0; s < NSTEPS; s++) {
        lstm_step_kernel<<<sgrid, sblk, DYN_SMEM>>>(yb, FEAT,
                                                    h0[s & 1], 544, W0p, b0p, c0, h0[(s + 1) & 1]);
        lstm_step_kernel<<<sgrid, sblk, DYN_SMEM>>>(h0[(s + 1) & 1], HID,
                                                    h1[s & 1], 1024, W1p, b1p, c1, h1[(s + 1) & 1]);
        dec_out_kernel<<<128, 256>>>(h1[(s + 1) & 1], yb, dec_b, s);
    }

    deconv_kernel<<<B_SZ, 64>>>(deconvw, (float*)d_out);
}